// round 1
// baseline (speedup 1.0000x reference)
#include <cuda_runtime.h>

#define IS      256
#define TILE    16
#define FACES   4096
#define NBATCH  4
#define ROUND   256
#define NEAR_P  0.1f
#define FAR_P   100.0f
#define TINYF   1e-12f
#define EPSV    0.001f

__global__ __launch_bounds__(256) void raster_kernel(
    const float* __restrict__ faces,   // (B, F, 3, 3)
    const float* __restrict__ tex,     // (B, F, 4, 4, 4, 3)
    float* __restrict__ out)           // (B, IS, IS, 5)
{
    __shared__ float smF[ROUND * 9];
    __shared__ float smA0[ROUND], smB0[ROUND], smC0[ROUND];
    __shared__ float smA1[ROUND], smB1[ROUND], smC1[ROUND];
    __shared__ float smA2[ROUND], smB2[ROUND], smC2[ROUND];
    __shared__ float smRZ0[ROUND], smRZ1[ROUND], smRZ2[ROUND];
    __shared__ int   smIdx[ROUND];
    __shared__ int   smCnt[8];
    __shared__ int   smTot;

    const int tid = threadIdx.x;
    const int b   = blockIdx.z;
    const int lx  = tid & 15;
    const int ly  = tid >> 4;
    const int px  = blockIdx.x * TILE + lx;
    const int py  = blockIdx.y * TILE + ly;

    const float xp = (2.0f * px + 1.0f - IS) * (1.0f / IS);
    const float yp = (2.0f * py + 1.0f - IS) * (1.0f / IS);
    const float xlo = (2.0f * (blockIdx.x * TILE)            + 1.0f - IS) * (1.0f / IS);
    const float xhi = (2.0f * (blockIdx.x * TILE + TILE - 1) + 1.0f - IS) * (1.0f / IS);
    const float ylo = (2.0f * (blockIdx.y * TILE)            + 1.0f - IS) * (1.0f / IS);
    const float yhi = (2.0f * (blockIdx.y * TILE + TILE - 1) + 1.0f - IS) * (1.0f / IS);

    const float* fb = faces + (size_t)b * FACES * 9;

    float bestInv = 0.0f;   // max 1/zp among valid candidates
    int   bestF   = -1;

    for (int base = 0; base < FACES; base += ROUND) {
        __syncthreads();
        // cooperative coalesced load of 256 faces
        #pragma unroll
        for (int i = 0; i < 9; i++)
            smF[i * 256 + tid] = fb[base * 9 + i * 256 + tid];
        __syncthreads();

        const float x0 = smF[tid * 9 + 0], y0 = smF[tid * 9 + 1], z0 = smF[tid * 9 + 2];
        const float x1 = smF[tid * 9 + 3], y1 = smF[tid * 9 + 4], z1 = smF[tid * 9 + 5];
        const float x2 = smF[tid * 9 + 6], y2 = smF[tid * 9 + 7], z2 = smF[tid * 9 + 8];

        const float xmn = fminf(x0, fminf(x1, x2)), xmx = fmaxf(x0, fmaxf(x1, x2));
        const float ymn = fminf(y0, fminf(y1, y2)), ymx = fmaxf(y0, fmaxf(y1, y2));
        const bool p = (xmn <= xhi) && (xmx >= xlo) && (ymn <= yhi) && (ymx >= ylo);

        const unsigned m = __ballot_sync(0xffffffffu, p);
        const int warp = tid >> 5, lane = tid & 31;
        if (lane == 0) smCnt[warp] = __popc(m);
        __syncthreads();

        int ofs = 0;
        #pragma unroll
        for (int w = 0; w < 8; w++)
            if (w < warp) ofs += smCnt[w];
        if (tid == 0)
            smTot = smCnt[0] + smCnt[1] + smCnt[2] + smCnt[3] +
                    smCnt[4] + smCnt[5] + smCnt[6] + smCnt[7];

        if (p) {
            const int pos = ofs + __popc(m & ((1u << lane) - 1u));
            smA0[pos] = y1 - y2; smB0[pos] = x2 - x1; smC0[pos] = x1 * y2 - x2 * y1;
            smA1[pos] = y2 - y0; smB1[pos] = x0 - x2; smC1[pos] = x2 * y0 - x0 * y2;
            smA2[pos] = y0 - y1; smB2[pos] = x1 - x0; smC2[pos] = x0 * y1 - x1 * y0;
            smRZ0[pos] = 1.0f / z0; smRZ1[pos] = 1.0f / z1; smRZ2[pos] = 1.0f / z2;
            smIdx[pos] = base + tid;
        }
        __syncthreads();

        const int n = smTot;
        for (int c = 0; c < n; c++) {
            const float w0 = fmaf(yp, smB0[c], fmaf(xp, smA0[c], smC0[c]));
            const float w1 = fmaf(yp, smB1[c], fmaf(xp, smA1[c], smC1[c]));
            const float w2 = fmaf(yp, smB2[c], fmaf(xp, smA2[c], smC2[c]));
            const float det = w0 + w1 + w2;
            const bool inside = (fabsf(det) > TINYF) &&
                ((w0 > 0.f && w1 > 0.f && w2 > 0.f) ||
                 (w0 < 0.f && w1 < 0.f && w2 < 0.f));
            if (inside) {
                const float num = w0 * smRZ0[c] + w1 * smRZ1[c] + w2 * smRZ2[c];
                float inv = num / det;           // = 1/zp  (positive when inside)
                if (!(fabsf(inv) > TINYF)) inv = 1.0f;
                if (inv > (1.0f / FAR_P) && inv < (1.0f / NEAR_P) && inv > bestInv) {
                    bestInv = inv;
                    bestF   = smIdx[c];
                }
            }
        }
    }

    // -------- shading --------
    float r = 0.f, g = 0.f, bl = 0.f, alpha = 0.f, depth = FAR_P;
    if (bestF >= 0) {
        const float* fv = fb + (size_t)bestF * 9;
        const float x0 = fv[0], y0 = fv[1], z0 = fv[2];
        const float x1 = fv[3], y1 = fv[4], z1 = fv[5];
        const float x2 = fv[6], y2 = fv[7], z2 = fv[8];

        const float w0 = yp * (x2 - x1) + xp * (y1 - y2) + (x1 * y2 - x2 * y1);
        const float w1 = yp * (x0 - x2) + xp * (y2 - y0) + (x2 * y0 - x0 * y2);
        const float w2 = yp * (x1 - x0) + xp * (y0 - y1) + (x0 * y1 - x1 * y0);
        float det = w0 + w1 + w2;
        if (!(fabsf(det) > TINYF)) det = 1.0f;
        float n0 = w0 / det, n1 = w1 / det, n2 = w2 / det;
        n0 = fminf(fmaxf(n0, 0.f), 1.f);
        n1 = fminf(fmaxf(n1, 0.f), 1.f);
        n2 = fminf(fmaxf(n2, 0.f), 1.f);
        float s = n0 + n1 + n2;
        if (!(s > TINYF)) s = 1.0f;
        n0 /= s; n1 /= s; n2 /= s;
        float invz = n0 / z0 + n1 / z1 + n2 / z2;
        if (!(fabsf(invz) > TINYF)) invz = 1.0f;
        const float zp = 1.0f / invz;
        depth = zp;
        alpha = 1.0f;

        const float hi = 3.0f - EPSV;   // T-1-EPS, T=4
        const float t0 = fminf(fmaxf(n0 * 3.0f * zp / z0, 0.f), hi);
        const float t1 = fminf(fmaxf(n1 * 3.0f * zp / z1, 0.f), hi);
        const float t2 = fminf(fmaxf(n2 * 3.0f * zp / z2, 0.f), hi);
        const float l0f = floorf(t0), l1f = floorf(t1), l2f = floorf(t2);
        const float f0 = t0 - l0f, f1 = t1 - l1f, f2 = t2 - l2f;
        const int l0 = (int)l0f, l1 = (int)l1f, l2 = (int)l2f;

        const float* tp = tex + ((size_t)b * FACES + bestF) * 192;  // 4*4*4*3
        #pragma unroll
        for (int d0 = 0; d0 < 2; d0++) {
            const float wx = d0 ? f0 : 1.0f - f0;
            #pragma unroll
            for (int d1 = 0; d1 < 2; d1++) {
                const float wy = wx * (d1 ? f1 : 1.0f - f1);
                #pragma unroll
                for (int d2 = 0; d2 < 2; d2++) {
                    const float wgt = wy * (d2 ? f2 : 1.0f - f2);
                    const int idx = ((l0 + d0) * 16 + (l1 + d1) * 4 + (l2 + d2)) * 3;
                    r  += wgt * tp[idx + 0];
                    g  += wgt * tp[idx + 1];
                    bl += wgt * tp[idx + 2];
                }
            }
        }
    }

    float* o = out + (((size_t)b * IS + py) * IS + px) * 5;
    o[0] = r; o[1] = g; o[2] = bl; o[3] = alpha; o[4] = depth;
}

extern "C" void kernel_launch(void* const* d_in, const int* in_sizes, int n_in,
                              void* d_out, int out_size)
{
    const float* faces = (const float*)d_in[0];
    const float* tex   = (const float*)d_in[1];
    float* out         = (float*)d_out;

    dim3 grid(IS / TILE, IS / TILE, NBATCH);
    raster_kernel<<<grid, 256>>>(faces, tex, out);
}

// round 2
// speedup vs baseline: 1.8633x; 1.8633x over previous
#include <cuda_runtime.h>

#define IS      256
#define TILE    16
#define NTX     (IS / TILE)      // 16 tiles per dim
#define FACES   4096
#define NBATCH  4
#define NEAR_P  0.1f
#define FAR_P   100.0f
#define TINYF   1e-12f
#define EPSV    0.001f
#define BINCAP  2048
#define NBINS   (NBATCH * NTX * NTX)

__device__ float4 g_c0[NBATCH * FACES];
__device__ float4 g_c1[NBATCH * FACES];
__device__ float4 g_c2[NBATCH * FACES];
__device__ int    g_binCnt[NBINS];
__device__ int    g_binList[NBINS * BINCAP];

__global__ void zero_kernel()
{
    g_binCnt[threadIdx.x] = 0;
}

__global__ __launch_bounds__(256) void setup_kernel(const float* __restrict__ faces)
{
    const int id = blockIdx.x * 256 + threadIdx.x;   // 0 .. B*F-1
    const int b  = id >> 12;
    const int f  = id & (FACES - 1);

    const float* fv = faces + (size_t)id * 9;
    const float x0 = fv[0], y0 = fv[1], z0 = fv[2];
    const float x1 = fv[3], y1 = fv[4], z1 = fv[5];
    const float x2 = fv[6], y2 = fv[7], z2 = fv[8];

    g_c0[id] = make_float4(y1 - y2, x2 - x1, x1 * y2 - x2 * y1, 1.0f / z0);
    g_c1[id] = make_float4(y2 - y0, x0 - x2, x2 * y0 - x0 * y2, 1.0f / z1);
    g_c2[id] = make_float4(y0 - y1, x1 - x0, x0 * y1 - x1 * y0, 1.0f / z2);

    const float xmn = fminf(x0, fminf(x1, x2)), xmx = fmaxf(x0, fmaxf(x1, x2));
    const float ymn = fminf(y0, fminf(y1, y2)), ymx = fmaxf(y0, fmaxf(y1, y2));

    // pixel center xp = (2*px + 1 - IS)/IS  =>  px = (IS*xp + IS-1)/2 ; widen 1px
    int pxlo = (int)ceilf ((xmn * IS + (IS - 1)) * 0.5f) - 1;
    int pxhi = (int)floorf((xmx * IS + (IS - 1)) * 0.5f) + 1;
    int pylo = (int)ceilf ((ymn * IS + (IS - 1)) * 0.5f) - 1;
    int pyhi = (int)floorf((ymx * IS + (IS - 1)) * 0.5f) + 1;
    pxlo = max(pxlo, 0); pxhi = min(pxhi, IS - 1);
    pylo = max(pylo, 0); pyhi = min(pyhi, IS - 1);
    if (pxlo > pxhi || pylo > pyhi) return;

    const int txlo = pxlo >> 4, txhi = pxhi >> 4;
    const int tylo = pylo >> 4, tyhi = pyhi >> 4;
    for (int ty = tylo; ty <= tyhi; ty++)
        for (int tx = txlo; tx <= txhi; tx++) {
            const int bin = (b * NTX + ty) * NTX + tx;
            const int pos = atomicAdd(&g_binCnt[bin], 1);
            if (pos < BINCAP) g_binList[bin * BINCAP + pos] = f;
        }
}

__global__ __launch_bounds__(256) void raster_kernel(
    const float* __restrict__ faces,
    const float* __restrict__ tex,
    float* __restrict__ out)
{
    __shared__ float4 sc0[256], sc1[256], sc2[256];
    __shared__ int    sidx[256];

    const int tid = threadIdx.x;
    const int b   = blockIdx.z;
    const int px  = blockIdx.x * TILE + (tid & 15);
    const int py  = blockIdx.y * TILE + (tid >> 4);

    const float xp = (2.0f * px + 1.0f - IS) * (1.0f / IS);
    const float yp = (2.0f * py + 1.0f - IS) * (1.0f / IS);

    const int bin = (b * NTX + blockIdx.y) * NTX + blockIdx.x;
    const int n   = min(g_binCnt[bin], BINCAP);

    float bestInv = 0.0f;
    int   bestF   = -1;

    for (int start = 0; start < n; start += 256) {
        const int cnt = min(256, n - start);
        __syncthreads();
        if (tid < cnt) {
            const int f  = g_binList[bin * BINCAP + start + tid];
            const int id = b * FACES + f;
            sc0[tid] = g_c0[id];
            sc1[tid] = g_c1[id];
            sc2[tid] = g_c2[id];
            sidx[tid] = f;
        }
        __syncthreads();

        for (int c = 0; c < cnt; c++) {
            const float4 a0 = sc0[c];
            const float4 a1 = sc1[c];
            const float4 a2 = sc2[c];
            const float w0 = fmaf(xp, a0.x, fmaf(yp, a0.y, a0.z));
            const float w1 = fmaf(xp, a1.x, fmaf(yp, a1.y, a1.z));
            const float w2 = fmaf(xp, a2.x, fmaf(yp, a2.y, a2.z));
            const float det = w0 + w1 + w2;
            const bool inside = (fabsf(det) > TINYF) &&
                ((w0 > 0.f && w1 > 0.f && w2 > 0.f) ||
                 (w0 < 0.f && w1 < 0.f && w2 < 0.f));
            if (inside) {
                const float num = w0 * a0.w + w1 * a1.w + w2 * a2.w;
                float inv = num / det;              // = 1/zp, positive when inside
                if (!(fabsf(inv) > TINYF)) inv = 1.0f;
                if (inv > (1.0f / FAR_P) && inv < (1.0f / NEAR_P)) {
                    const int f = sidx[c];
                    if (inv > bestInv || (inv == bestInv && f < bestF)) {
                        bestInv = inv;
                        bestF   = f;
                    }
                }
            }
        }
    }

    // -------- shading --------
    float r = 0.f, g = 0.f, bl = 0.f, alpha = 0.f, depth = FAR_P;
    if (bestF >= 0) {
        const float* fv = faces + ((size_t)b * FACES + bestF) * 9;
        const float x0 = fv[0], y0 = fv[1], z0 = fv[2];
        const float x1 = fv[3], y1 = fv[4], z1 = fv[5];
        const float x2 = fv[6], y2 = fv[7], z2 = fv[8];

        const float w0 = yp * (x2 - x1) + xp * (y1 - y2) + (x1 * y2 - x2 * y1);
        const float w1 = yp * (x0 - x2) + xp * (y2 - y0) + (x2 * y0 - x0 * y2);
        const float w2 = yp * (x1 - x0) + xp * (y0 - y1) + (x0 * y1 - x1 * y0);
        float det = w0 + w1 + w2;
        if (!(fabsf(det) > TINYF)) det = 1.0f;
        float n0 = w0 / det, n1 = w1 / det, n2 = w2 / det;
        n0 = fminf(fmaxf(n0, 0.f), 1.f);
        n1 = fminf(fmaxf(n1, 0.f), 1.f);
        n2 = fminf(fmaxf(n2, 0.f), 1.f);
        float s = n0 + n1 + n2;
        if (!(s > TINYF)) s = 1.0f;
        n0 /= s; n1 /= s; n2 /= s;
        float invz = n0 / z0 + n1 / z1 + n2 / z2;
        if (!(fabsf(invz) > TINYF)) invz = 1.0f;
        const float zp = 1.0f / invz;
        depth = zp;
        alpha = 1.0f;

        const float hi = 3.0f - EPSV;   // T-1-EPS, T=4
        const float t0 = fminf(fmaxf(n0 * 3.0f * zp / z0, 0.f), hi);
        const float t1 = fminf(fmaxf(n1 * 3.0f * zp / z1, 0.f), hi);
        const float t2 = fminf(fmaxf(n2 * 3.0f * zp / z2, 0.f), hi);
        const float l0f = floorf(t0), l1f = floorf(t1), l2f = floorf(t2);
        const float f0 = t0 - l0f, f1 = t1 - l1f, f2 = t2 - l2f;
        const int l0 = (int)l0f, l1 = (int)l1f, l2 = (int)l2f;

        const float* tp = tex + ((size_t)b * FACES + bestF) * 192;
        #pragma unroll
        for (int d0 = 0; d0 < 2; d0++) {
            const float wx = d0 ? f0 : 1.0f - f0;
            #pragma unroll
            for (int d1 = 0; d1 < 2; d1++) {
                const float wy = wx * (d1 ? f1 : 1.0f - f1);
                #pragma unroll
                for (int d2 = 0; d2 < 2; d2++) {
                    const float wgt = wy * (d2 ? f2 : 1.0f - f2);
                    const int idx = ((l0 + d0) * 16 + (l1 + d1) * 4 + (l2 + d2)) * 3;
                    r  += wgt * tp[idx + 0];
                    g  += wgt * tp[idx + 1];
                    bl += wgt * tp[idx + 2];
                }
            }
        }
    }

    float* o = out + (((size_t)b * IS + py) * IS + px) * 5;
    o[0] = r; o[1] = g; o[2] = bl; o[3] = alpha; o[4] = depth;
}

extern "C" void kernel_launch(void* const* d_in, const int* in_sizes, int n_in,
                              void* d_out, int out_size)
{
    const float* faces = (const float*)d_in[0];
    const float* tex   = (const float*)d_in[1];
    float* out         = (float*)d_out;

    zero_kernel<<<1, NBINS>>>();
    setup_kernel<<<(NBATCH * FACES) / 256, 256>>>(faces);
    dim3 grid(NTX, NTX, NBATCH);
    raster_kernel<<<grid, 256>>>(faces, tex, out);
}